// round 11
// baseline (speedup 1.0000x reference)
#include <cuda_runtime.h>

// Problem constants
#define BB      256      // batch
#define SEQ     196
#define DD      768
#define D4      192      // DD/4 float4 per row
#define NPOOL   20       // per pool
#define NKEYS   40       // 20 s-keys + 20 m-keys
#define KK      4        // top-k
#define BLK     3840     // LEN*H*DH floats per selected pool entry
#define BLK4    960      // BLK/4
#define PER_LB  15360    // KK * BLK floats per (layer, batch)
#define PER_LB4 3840     // PER_LB/4
#define L2N     24       // num_layers * 2
#define NSIM    256      // sim blocks (one per batch)
#define NGU     (2 * L2N * BB)   // 12288 gather units

// Device-global scratch (no allocations; zero-initialized at load)
__device__ int          g_run;
__device__ volatile int g_flag[BB];
__device__ int          g_sidx[BB * KK];
__device__ int          g_midx[BB * KK];
__device__ float        g_bsum_s[BB];
__device__ float        g_bsum_m[BB];

// ---------------------------------------------------------------------------
// Epoch bump — makes the per-batch ready flags replay-safe (flag==g_run).
// ---------------------------------------------------------------------------
__global__ void bump_kernel() { g_run = g_run + 1; }

// ---------------------------------------------------------------------------
// Fused kernel. Blocks 0..255: per-batch mean + normalize + 40 sims (with
// on-the-fly key normalization) + top-4; publish indices, release flag.
// Blocks 256..: gather units (which,l,b) — spin on flag[b], then stream the
// 4 selected 15KB chunks to the output with __stcs. Block g==0 also reduces
// the two output scalars after waiting on all flags.
// __launch_bounds__(768,2) guarantees all 256 sim blocks are resident in
// wave 1 (296 slots) -> no spin deadlock.
// ---------------------------------------------------------------------------
__global__ void __launch_bounds__(768, 2)
fused_kernel(const float4* __restrict__ x,
             const float4* __restrict__ skey,
             const float4* __restrict__ mkey,
             const float4* __restrict__ s_prompt,
             const float4* __restrict__ m_prompt,
             float4* __restrict__ out,
             float* __restrict__ out_scalars) {
    int bid = blockIdx.x;
    int t = threadIdx.x;            // 0..767
    int run = g_run;                // written by bump_kernel (stream-ordered)

    __shared__ float4 sh4[768];     // sim partial sums (12 KB)
    __shared__ float4 sh_x4[D4];    // normalized mean
    __shared__ float  shw[8];
    __shared__ float  sh_sim[NKEYS];

    if (bid < NSIM) {
        // ----------------- SIM PATH (batch b = bid) -----------------
        int b = bid;
        int q = t / D4;             // row quarter (49 rows each)
        int c4 = t % D4;

        const float4* src = x + (size_t)b * (SEQ * D4) + (size_t)(q * 49) * D4 + c4;
        float4 acc = make_float4(0.f, 0.f, 0.f, 0.f);
        #pragma unroll 7
        for (int r = 0; r < 49; ++r) {
            float4 v = src[(size_t)r * D4];
            acc.x += v.x; acc.y += v.y; acc.z += v.z; acc.w += v.w;
        }
        sh4[t] = acc;
        __syncthreads();

        float sq = 0.f;
        if (t < D4) {
            float4 a = sh4[t], b1 = sh4[t + D4], c = sh4[t + 2 * D4], d = sh4[t + 3 * D4];
            float4 m;
            m.x = (a.x + b1.x + c.x + d.x) * (1.0f / SEQ);
            m.y = (a.y + b1.y + c.y + d.y) * (1.0f / SEQ);
            m.z = (a.z + b1.z + c.z + d.z) * (1.0f / SEQ);
            m.w = (a.w + b1.w + c.w + d.w) * (1.0f / SEQ);
            sh_x4[t] = m;
            sq = m.x * m.x + m.y * m.y + m.z * m.z + m.w * m.w;
        }
        #pragma unroll
        for (int o = 16; o > 0; o >>= 1) sq += __shfl_down_sync(0xffffffffu, sq, o);
        if (t < D4 && (t & 31) == 0) shw[t >> 5] = sq;
        __syncthreads();
        if (t < 32) {
            float v = (t < 6) ? shw[t] : 0.f;
            #pragma unroll
            for (int o = 4; o > 0; o >>= 1) v += __shfl_down_sync(0xffffffffu, v, o);
            if (t == 0) shw[0] = v;
        }
        __syncthreads();
        float inv = rsqrtf(fmaxf(shw[0], 1e-12f));
        if (t < D4) {
            float4 m = sh_x4[t];
            m.x *= inv; m.y *= inv; m.z *= inv; m.w *= inv;
            sh_x4[t] = m;
        }
        __syncthreads();

        int warp = t >> 5, lane = t & 31;
        for (int p = warp; p < NKEYS; p += 24) {
            const float4* kp = (p < NPOOL) ? (skey + (size_t)p * D4)
                                           : (mkey + (size_t)(p - NPOOL) * D4);
            float dot = 0.f, kk = 0.f;
            #pragma unroll
            for (int i = lane; i < D4; i += 32) {
                float4 xv = sh_x4[i], kv = __ldg(&kp[i]);
                dot += xv.x * kv.x + xv.y * kv.y + xv.z * kv.z + xv.w * kv.w;
                kk  += kv.x * kv.x + kv.y * kv.y + kv.z * kv.z + kv.w * kv.w;
            }
            #pragma unroll
            for (int o = 16; o > 0; o >>= 1) {
                dot += __shfl_down_sync(0xffffffffu, dot, o);
                kk  += __shfl_down_sync(0xffffffffu, kk, o);
            }
            if (lane == 0) sh_sim[p] = dot * rsqrtf(fmaxf(kk, 1e-12f));
        }
        __syncthreads();

        // Top-4 (descending, first-index ties). t=0: s, t=1: m.
        if (t < 2) {
            const float* sims = sh_sim + t * NPOOL;
            int* idx = t ? g_midx : g_sidx;
            float v[NPOOL];
            #pragma unroll
            for (int j = 0; j < NPOOL; ++j) v[j] = sims[j];
            float sum = 0.f;
            #pragma unroll
            for (int k = 0; k < KK; ++k) {
                float best = -1e30f; int bi = 0;
                #pragma unroll
                for (int j = 0; j < NPOOL; ++j) if (v[j] > best) { best = v[j]; bi = j; }
                idx[b * KK + k] = bi;
                sum += best;
                v[bi] = -1e30f;
            }
            if (t) g_bsum_m[b] = sum; else g_bsum_s[b] = sum;
        }
        __syncthreads();
        __threadfence();                      // publish idx/bsum before flag
        if (t == 0) g_flag[b] = run;          // release
        return;
    }

    // ----------------- GATHER PATH -----------------
    int g = bid - NSIM;                       // 0..12287
    int which = g >= (L2N * BB);
    int lb = which ? g - L2N * BB : g;
    int l = lb >> 8;
    int b = lb & 255;

    if (g == 0) {
        // Wait for ALL batches, then reduce the two scalars (fixed tree).
        if (t < BB) {
            while (g_flag[t] != run) __nanosleep(200);
        }
        __syncthreads();
        __threadfence();
        __shared__ float shs[8], shm[8];
        float ssum = (t < BB) ? g_bsum_s[t] : 0.f;
        float msum = (t < BB) ? g_bsum_m[t] : 0.f;
        #pragma unroll
        for (int o = 16; o > 0; o >>= 1) {
            ssum += __shfl_down_sync(0xffffffffu, ssum, o);
            msum += __shfl_down_sync(0xffffffffu, msum, o);
        }
        if (t < BB && (t & 31) == 0) { shs[t >> 5] = ssum; shm[t >> 5] = msum; }
        __syncthreads();
        if (t == 0) {
            float sv = 0.f, mv = 0.f;
            #pragma unroll
            for (int w = 0; w < 8; ++w) { sv += shs[w]; mv += shm[w]; }
            out_scalars[0] = sv * (1.0f / BB);
            out_scalars[1] = mv * (1.0f / BB);
        }
    } else {
        if (t == 0) {
            while (g_flag[b] != run) __nanosleep(200);
        }
        __syncthreads();
        __threadfence();                      // acquire: idx visible
    }

    const int* idx = which ? g_midx : g_sidx;
    const float4* prompt = which ? m_prompt : s_prompt;
    const float4* lbase = prompt + (size_t)l * NPOOL * BLK4;

    int id0 = idx[b * KK + 0], id1 = idx[b * KK + 1],
        id2 = idx[b * KK + 2], id3 = idx[b * KK + 3];

    // dst layout: out[(which,l,b)] == out + g*PER_LB4 (matches reference).
    float4* dst = out + (size_t)g * PER_LB4;
    #pragma unroll
    for (int i = 0; i < 5; ++i) {
        int j = t + i * 768;                  // 0..3839
        int k = j / BLK4;                     // chunk 0..3
        int o = j - k * BLK4;
        int id = (k == 0) ? id0 : (k == 1) ? id1 : (k == 2) ? id2 : id3;
        float4 v = __ldg(&lbase[(size_t)id * BLK4 + o]);
        __stcs(&dst[j], v);                   // streaming store
    }
}

// ---------------------------------------------------------------------------
extern "C" void kernel_launch(void* const* d_in, const int* in_sizes, int n_in,
                              void* d_out, int out_size) {
    const float* x_embed = (const float*)d_in[0];  // [256,196,768]
    const float* s_prompt = (const float*)d_in[1]; // [24,20,5,12,64]
    const float* m_prompt = (const float*)d_in[2]; // [24,20,5,12,64]
    const float* s_key = (const float*)d_in[3];    // [20,768]
    const float* m_key = (const float*)d_in[4];    // [20,768]
    float* out = (float*)d_out;

    const size_t S_ELEMS = (size_t)L2N * BB * PER_LB;  // 94,371,840
    float* out_scalars = out + 2 * S_ELEMS;

    bump_kernel<<<1, 1>>>();
    fused_kernel<<<NSIM + NGU, 768>>>((const float4*)x_embed,
                                      (const float4*)s_key,
                                      (const float4*)m_key,
                                      (const float4*)s_prompt,
                                      (const float4*)m_prompt,
                                      (float4*)out, out_scalars);
}

// round 12
// speedup vs baseline: 1.2772x; 1.2772x over previous
#include <cuda_runtime.h>

// Problem constants
#define BB     256      // batch
#define SEQ    196
#define DD     768
#define D4     192      // DD/4 float4 per row
#define NPOOL  20       // per pool
#define NKEYS  40       // 20 s-keys + 20 m-keys
#define KK     4        // top-k
#define BLK    3840     // LEN*H*DH = 5*12*64 floats per selected pool entry
#define BLK8   480      // BLK/8 float8-groups per chunk
#define PER_LB 15360    // KK * BLK floats per (layer, batch)
#define L2N    24       // num_layers * 2

// Device-global scratch (no allocations allowed)
__device__ int   g_sidx[BB * KK];
__device__ int   g_midx[BB * KK];
__device__ float g_bsum_s[BB];         // per-batch sum of top-4 s sims
__device__ float g_bsum_m[BB];         // per-batch sum of top-4 m sims

// 256-bit global load (non-coherent) / streaming store — sm_100+ PTX.
__device__ __forceinline__ void ldg_nc_v8(const float* p, float* v) {
    asm volatile("ld.global.nc.v8.f32 {%0,%1,%2,%3,%4,%5,%6,%7}, [%8];"
                 : "=f"(v[0]), "=f"(v[1]), "=f"(v[2]), "=f"(v[3]),
                   "=f"(v[4]), "=f"(v[5]), "=f"(v[6]), "=f"(v[7])
                 : "l"(p));
}
__device__ __forceinline__ void stg_cs_v8(float* p, const float* v) {
    asm volatile("st.global.cs.v8.f32 [%0], {%1,%2,%3,%4,%5,%6,%7,%8};"
                 :: "l"(p),
                    "f"(v[0]), "f"(v[1]), "f"(v[2]), "f"(v[3]),
                    "f"(v[4]), "f"(v[5]), "f"(v[6]), "f"(v[7])
                 : "memory");
}

// ---------------------------------------------------------------------------
// Kernel 1: fused per-batch mean (float4, 4 row-groups of 49) + L2-normalize
// + 40 similarity dots with on-the-fly key normalization + top-4 selection.
// EXACT R10 configuration (measured 29.8us). 256 blocks x 768 threads.
// ---------------------------------------------------------------------------
__global__ void batch_sim_topk_kernel(const float4* __restrict__ x,
                                      const float4* __restrict__ skey,
                                      const float4* __restrict__ mkey) {
    int b = blockIdx.x;
    int t = threadIdx.x;   // 0..767
    int q = t / D4;        // row quarter 0..3 (49 rows each)
    int c4 = t % D4;       // float4 column 0..191

    __shared__ float4 sh4[768];     // partial sums (12 KB)
    __shared__ float4 sh_x4[D4];    // normalized mean (3 KB)
    __shared__ float  shw[8];
    __shared__ float  sh_sim[NKEYS];

    const float4* src = x + (size_t)b * (SEQ * D4) + (size_t)(q * 49) * D4 + c4;
    float4 acc = make_float4(0.f, 0.f, 0.f, 0.f);
    #pragma unroll 7
    for (int r = 0; r < 49; ++r) {
        float4 v = src[(size_t)r * D4];
        acc.x += v.x; acc.y += v.y; acc.z += v.z; acc.w += v.w;
    }
    sh4[t] = acc;
    __syncthreads();

    float sq = 0.f;
    if (t < D4) {
        float4 a = sh4[t], b1 = sh4[t + D4], c = sh4[t + 2 * D4], d = sh4[t + 3 * D4];
        float4 m;
        m.x = (a.x + b1.x + c.x + d.x) * (1.0f / SEQ);
        m.y = (a.y + b1.y + c.y + d.y) * (1.0f / SEQ);
        m.z = (a.z + b1.z + c.z + d.z) * (1.0f / SEQ);
        m.w = (a.w + b1.w + c.w + d.w) * (1.0f / SEQ);
        sh_x4[t] = m;
        sq = m.x * m.x + m.y * m.y + m.z * m.z + m.w * m.w;
    }
    #pragma unroll
    for (int o = 16; o > 0; o >>= 1) sq += __shfl_down_sync(0xffffffffu, sq, o);
    if (t < D4 && (t & 31) == 0) shw[t >> 5] = sq;
    __syncthreads();
    if (t < 32) {
        float v = (t < 6) ? shw[t] : 0.f;
        #pragma unroll
        for (int o = 4; o > 0; o >>= 1) v += __shfl_down_sync(0xffffffffu, v, o);
        if (t == 0) shw[0] = v;
    }
    __syncthreads();
    float inv = rsqrtf(fmaxf(shw[0], 1e-12f));
    if (t < D4) {
        float4 m = sh_x4[t];
        m.x *= inv; m.y *= inv; m.z *= inv; m.w *= inv;
        sh_x4[t] = m;
    }
    __syncthreads();

    int warp = t >> 5, lane = t & 31;
    for (int p = warp; p < NKEYS; p += 24) {
        const float4* kp = (p < NPOOL) ? (skey + (size_t)p * D4)
                                       : (mkey + (size_t)(p - NPOOL) * D4);
        float dot = 0.f, kk = 0.f;
        #pragma unroll
        for (int i = lane; i < D4; i += 32) {
            float4 xv = sh_x4[i], kv = __ldg(&kp[i]);
            dot += xv.x * kv.x + xv.y * kv.y + xv.z * kv.z + xv.w * kv.w;
            kk  += kv.x * kv.x + kv.y * kv.y + kv.z * kv.z + kv.w * kv.w;
        }
        #pragma unroll
        for (int o = 16; o > 0; o >>= 1) {
            dot += __shfl_down_sync(0xffffffffu, dot, o);
            kk  += __shfl_down_sync(0xffffffffu, kk, o);
        }
        if (lane == 0) sh_sim[p] = dot * rsqrtf(fmaxf(kk, 1e-12f));
    }
    __syncthreads();

    // Top-4 (descending, first-index ties — strict > scan from j=0).
    if (t < 2) {
        const float* sims = sh_sim + t * NPOOL;
        int* idx = t ? g_midx : g_sidx;
        float v[NPOOL];
        #pragma unroll
        for (int j = 0; j < NPOOL; ++j) v[j] = sims[j];
        float sum = 0.f;
        #pragma unroll
        for (int k = 0; k < KK; ++k) {
            float best = -1e30f; int bi = 0;
            #pragma unroll
            for (int j = 0; j < NPOOL; ++j) if (v[j] > best) { best = v[j]; bi = j; }
            idx[b * KK + k] = bi;
            sum += best;
            v[bi] = -1e30f;
        }
        if (t) g_bsum_m[b] = sum; else g_bsum_s[b] = sum;
    }
}

// ---------------------------------------------------------------------------
// Kernel 2: the gather — R8/R10 structure (grid 6144 x 256, two launches,
// block 0 of s-launch folds the scalar reduction) but with 256-bit
// ld.global.nc.v8 / st.global.cs.v8: half the memory instructions per byte.
// Per chunk: 480 float8-groups -> iter1 all 256 threads, iter2 first 224.
// All addresses 32B-aligned (chunk bases are multiples of 15360B).
// ---------------------------------------------------------------------------
__global__ void gather_kernel(const float* __restrict__ prompt,
                              float* __restrict__ out, int which,
                              float* __restrict__ out_scalars) {
    int lb = blockIdx.x;
    int l = lb >> 8;          // / 256
    int b = lb & 255;
    int t = threadIdx.x;

    if (which == 0 && lb == 0) {
        float ssum = g_bsum_s[t];
        float msum = g_bsum_m[t];
        __shared__ float shs[8], shm[8];
        #pragma unroll
        for (int o = 16; o > 0; o >>= 1) {
            ssum += __shfl_down_sync(0xffffffffu, ssum, o);
            msum += __shfl_down_sync(0xffffffffu, msum, o);
        }
        if ((t & 31) == 0) { shs[t >> 5] = ssum; shm[t >> 5] = msum; }
        __syncthreads();
        if (t < 8) {
            float s = shs[t], m = shm[t];
            #pragma unroll
            for (int o = 4; o > 0; o >>= 1) {
                s += __shfl_down_sync(0xffu, s, o);
                m += __shfl_down_sync(0xffu, m, o);
            }
            if (t == 0) {
                out_scalars[0] = s * (1.0f / BB);
                out_scalars[1] = m * (1.0f / BB);
            }
        }
    }

    const int* idx = which ? g_midx : g_sidx;
    int i0 = idx[b * KK + 0], i1 = idx[b * KK + 1],
        i2 = idx[b * KK + 2], i3 = idx[b * KK + 3];
    int ids[4] = {i0, i1, i2, i3};

    float* dst = out + (size_t)lb * PER_LB;
    #pragma unroll
    for (int k = 0; k < 4; ++k) {
        const float* src = prompt + ((size_t)l * NPOOL + ids[k]) * BLK;
        float* dk = dst + k * BLK;
        float v[8];
        // iter 1: groups t (all 256 threads)
        ldg_nc_v8(src + (size_t)t * 8, v);
        stg_cs_v8(dk + (size_t)t * 8, v);
        // iter 2: groups 256 + t (first 224 threads)
        if (t < BLK8 - 256) {
            ldg_nc_v8(src + (size_t)(t + 256) * 8, v);
            stg_cs_v8(dk + (size_t)(t + 256) * 8, v);
        }
    }
}

// ---------------------------------------------------------------------------
extern "C" void kernel_launch(void* const* d_in, const int* in_sizes, int n_in,
                              void* d_out, int out_size) {
    const float* x_embed = (const float*)d_in[0];  // [256,196,768]
    const float* s_prompt = (const float*)d_in[1]; // [24,20,5,12,64]
    const float* m_prompt = (const float*)d_in[2]; // [24,20,5,12,64]
    const float* s_key = (const float*)d_in[3];    // [20,768]
    const float* m_key = (const float*)d_in[4];    // [20,768]
    float* out = (float*)d_out;

    const size_t S_ELEMS = (size_t)L2N * BB * PER_LB;  // 94,371,840
    float* out_scalars = out + 2 * S_ELEMS;

    batch_sim_topk_kernel<<<BB, 768>>>((const float4*)x_embed,
                                       (const float4*)s_key,
                                       (const float4*)m_key);
    gather_kernel<<<L2N * BB, 256>>>(s_prompt, out, 0, out_scalars);
    gather_kernel<<<L2N * BB, 256>>>(m_prompt, out + S_ELEMS, 1, out_scalars);
}

// round 13
// speedup vs baseline: 1.3461x; 1.0539x over previous
#include <cuda_runtime.h>

// Problem constants
#define BB     256      // batch
#define SEQ    196
#define DD     768
#define D4     192      // DD/4 float4 per row
#define NPOOL  20       // per pool
#define NKEYS  40       // 20 s-keys + 20 m-keys
#define KK     4        // top-k
#define BLK    3840     // LEN*H*DH = 5*12*64 floats per selected pool entry
#define BLK8   480      // BLK/8 float8-groups per chunk
#define PER_LB 15360    // KK * BLK floats per (layer, batch)
#define L2N    24       // num_layers * 2
#define NGB    (L2N * BB)   // 6144 gather blocks per pool

// Device-global scratch (no allocations allowed)
__device__ int   g_sidx[BB * KK];
__device__ int   g_midx[BB * KK];
__device__ float g_bsum_s[BB];         // per-batch sum of top-4 s sims
__device__ float g_bsum_m[BB];         // per-batch sum of top-4 m sims

// 256-bit global load (non-coherent) / streaming store — sm_100+ PTX.
__device__ __forceinline__ void ldg_nc_v8(const float* p, float* v) {
    asm volatile("ld.global.nc.v8.f32 {%0,%1,%2,%3,%4,%5,%6,%7}, [%8];"
                 : "=f"(v[0]), "=f"(v[1]), "=f"(v[2]), "=f"(v[3]),
                   "=f"(v[4]), "=f"(v[5]), "=f"(v[6]), "=f"(v[7])
                 : "l"(p));
}
__device__ __forceinline__ void stg_cs_v8(float* p, const float* v) {
    asm volatile("st.global.cs.v8.f32 [%0], {%1,%2,%3,%4,%5,%6,%7,%8};"
                 :: "l"(p),
                    "f"(v[0]), "f"(v[1]), "f"(v[2]), "f"(v[3]),
                    "f"(v[4]), "f"(v[5]), "f"(v[6]), "f"(v[7])
                 : "memory");
}

// ---------------------------------------------------------------------------
// Kernel 1: fused per-batch mean (float4, 4 row-groups of 49) + L2-normalize
// + 40 similarity dots with on-the-fly key normalization + top-4 selection.
// R10/R12 configuration (measured 29.8us) with __ldcs streaming reads of x
// (read-once stream; evict-first keeps L2 clean). 256 blocks x 768 threads.
// ---------------------------------------------------------------------------
__global__ void batch_sim_topk_kernel(const float4* __restrict__ x,
                                      const float4* __restrict__ skey,
                                      const float4* __restrict__ mkey) {
    int b = blockIdx.x;
    int t = threadIdx.x;   // 0..767
    int q = t / D4;        // row quarter 0..3 (49 rows each)
    int c4 = t % D4;       // float4 column 0..191

    __shared__ float4 sh4[768];     // partial sums (12 KB)
    __shared__ float4 sh_x4[D4];    // normalized mean (3 KB)
    __shared__ float  shw[8];
    __shared__ float  sh_sim[NKEYS];

    const float4* src = x + (size_t)b * (SEQ * D4) + (size_t)(q * 49) * D4 + c4;
    float4 acc = make_float4(0.f, 0.f, 0.f, 0.f);
    #pragma unroll 7
    for (int r = 0; r < 49; ++r) {
        float4 v = __ldcs(&src[(size_t)r * D4]);   // streaming (evict-first)
        acc.x += v.x; acc.y += v.y; acc.z += v.z; acc.w += v.w;
    }
    sh4[t] = acc;
    __syncthreads();

    float sq = 0.f;
    if (t < D4) {
        float4 a = sh4[t], b1 = sh4[t + D4], c = sh4[t + 2 * D4], d = sh4[t + 3 * D4];
        float4 m;
        m.x = (a.x + b1.x + c.x + d.x) * (1.0f / SEQ);
        m.y = (a.y + b1.y + c.y + d.y) * (1.0f / SEQ);
        m.z = (a.z + b1.z + c.z + d.z) * (1.0f / SEQ);
        m.w = (a.w + b1.w + c.w + d.w) * (1.0f / SEQ);
        sh_x4[t] = m;
        sq = m.x * m.x + m.y * m.y + m.z * m.z + m.w * m.w;
    }
    #pragma unroll
    for (int o = 16; o > 0; o >>= 1) sq += __shfl_down_sync(0xffffffffu, sq, o);
    if (t < D4 && (t & 31) == 0) shw[t >> 5] = sq;
    __syncthreads();
    if (t < 32) {
        float v = (t < 6) ? shw[t] : 0.f;
        #pragma unroll
        for (int o = 4; o > 0; o >>= 1) v += __shfl_down_sync(0xffffffffu, v, o);
        if (t == 0) shw[0] = v;
    }
    __syncthreads();
    float inv = rsqrtf(fmaxf(shw[0], 1e-12f));
    if (t < D4) {
        float4 m = sh_x4[t];
        m.x *= inv; m.y *= inv; m.z *= inv; m.w *= inv;
        sh_x4[t] = m;
    }
    __syncthreads();

    int warp = t >> 5, lane = t & 31;
    for (int p = warp; p < NKEYS; p += 24) {
        const float4* kp = (p < NPOOL) ? (skey + (size_t)p * D4)
                                       : (mkey + (size_t)(p - NPOOL) * D4);
        float dot = 0.f, kk = 0.f;
        #pragma unroll
        for (int i = lane; i < D4; i += 32) {
            float4 xv = sh_x4[i], kv = __ldg(&kp[i]);
            dot += xv.x * kv.x + xv.y * kv.y + xv.z * kv.z + xv.w * kv.w;
            kk  += kv.x * kv.x + kv.y * kv.y + kv.z * kv.z + kv.w * kv.w;
        }
        #pragma unroll
        for (int o = 16; o > 0; o >>= 1) {
            dot += __shfl_down_sync(0xffffffffu, dot, o);
            kk  += __shfl_down_sync(0xffffffffu, kk, o);
        }
        if (lane == 0) sh_sim[p] = dot * rsqrtf(fmaxf(kk, 1e-12f));
    }
    __syncthreads();

    // Top-4 (descending, first-index ties — strict > scan from j=0).
    if (t < 2) {
        const float* sims = sh_sim + t * NPOOL;
        int* idx = t ? g_midx : g_sidx;
        float v[NPOOL];
        #pragma unroll
        for (int j = 0; j < NPOOL; ++j) v[j] = sims[j];
        float sum = 0.f;
        #pragma unroll
        for (int k = 0; k < KK; ++k) {
            float best = -1e30f; int bi = 0;
            #pragma unroll
            for (int j = 0; j < NPOOL; ++j) if (v[j] > best) { best = v[j]; bi = j; }
            idx[b * KK + k] = bi;
            sum += best;
            v[bi] = -1e30f;
        }
        if (t) g_bsum_m[b] = sum; else g_bsum_s[b] = sum;
    }
}

// ---------------------------------------------------------------------------
// Kernel 2: fused gather — ONE launch for both pools, 256-thread blocks,
// inner loop bit-identical to R12's measured-good v8 version. Grid 12288:
// blocks [0,6144) = s-pool, [6144,12288) = m-pool; dst = out + g*PER_LB
// (s region then m region, matching the reference layout). Block 0 folds
// in the scalar reduction.
// ---------------------------------------------------------------------------
__global__ void gather_kernel(const float* __restrict__ s_prompt,
                              const float* __restrict__ m_prompt,
                              float* __restrict__ out,
                              float* __restrict__ out_scalars) {
    int g = blockIdx.x;               // 0..12287
    int which = g >= NGB;
    int lb = which ? g - NGB : g;
    int l = lb >> 8;                  // / 256
    int b = lb & 255;
    int t = threadIdx.x;

    if (g == 0) {
        float ssum = g_bsum_s[t];
        float msum = g_bsum_m[t];
        __shared__ float shs[8], shm[8];
        #pragma unroll
        for (int o = 16; o > 0; o >>= 1) {
            ssum += __shfl_down_sync(0xffffffffu, ssum, o);
            msum += __shfl_down_sync(0xffffffffu, msum, o);
        }
        if ((t & 31) == 0) { shs[t >> 5] = ssum; shm[t >> 5] = msum; }
        __syncthreads();
        if (t < 8) {
            float s = shs[t], m = shm[t];
            #pragma unroll
            for (int o = 4; o > 0; o >>= 1) {
                s += __shfl_down_sync(0xffu, s, o);
                m += __shfl_down_sync(0xffu, m, o);
            }
            if (t == 0) {
                out_scalars[0] = s * (1.0f / BB);
                out_scalars[1] = m * (1.0f / BB);
            }
        }
    }

    const int* idx = which ? g_midx : g_sidx;
    const float* prompt = which ? m_prompt : s_prompt;
    int i0 = idx[b * KK + 0], i1 = idx[b * KK + 1],
        i2 = idx[b * KK + 2], i3 = idx[b * KK + 3];
    int ids[4] = {i0, i1, i2, i3};

    float* dst = out + (size_t)g * PER_LB;
    #pragma unroll
    for (int k = 0; k < 4; ++k) {
        const float* src = prompt + ((size_t)l * NPOOL + ids[k]) * BLK;
        float* dk = dst + k * BLK;
        float v[8];
        // iter 1: groups t (all 256 threads)
        ldg_nc_v8(src + (size_t)t * 8, v);
        stg_cs_v8(dk + (size_t)t * 8, v);
        // iter 2: groups 256 + t (first 224 threads)
        if (t < BLK8 - 256) {
            ldg_nc_v8(src + (size_t)(t + 256) * 8, v);
            stg_cs_v8(dk + (size_t)(t + 256) * 8, v);
        }
    }
}

// ---------------------------------------------------------------------------
extern "C" void kernel_launch(void* const* d_in, const int* in_sizes, int n_in,
                              void* d_out, int out_size) {
    const float* x_embed = (const float*)d_in[0];  // [256,196,768]
    const float* s_prompt = (const float*)d_in[1]; // [24,20,5,12,64]
    const float* m_prompt = (const float*)d_in[2]; // [24,20,5,12,64]
    const float* s_key = (const float*)d_in[3];    // [20,768]
    const float* m_key = (const float*)d_in[4];    // [20,768]
    float* out = (float*)d_out;

    const size_t S_ELEMS = (size_t)L2N * BB * PER_LB;  // 94,371,840
    float* out_scalars = out + 2 * S_ELEMS;

    batch_sim_topk_kernel<<<BB, 768>>>((const float4*)x_embed,
                                       (const float4*)s_key,
                                       (const float4*)m_key);
    gather_kernel<<<2 * NGB, 256>>>(s_prompt, m_prompt, out, out_scalars);
}

// round 14
// speedup vs baseline: 1.3558x; 1.0072x over previous
#include <cuda_runtime.h>

// Problem constants
#define BB     256      // batch
#define SEQ    196
#define DD     768
#define D4     192      // DD/4 float4 per row
#define NPOOL  20       // per pool
#define NKEYS  40       // 20 s-keys + 20 m-keys
#define KK     4        // top-k
#define BLK    3840     // LEN*H*DH = 5*12*64 floats per selected pool entry
#define BLK8   480      // BLK/8 float8-groups per chunk
#define PER_LB 15360    // KK * BLK floats per (layer, batch)
#define L2N    24       // num_layers * 2
#define NGB    (L2N * BB)   // 6144 gather blocks per pool

// Device-global scratch (no allocations allowed)
__device__ int   g_sidx[BB * KK];
__device__ int   g_midx[BB * KK];
__device__ float g_bsum_s[BB];         // per-batch sum of top-4 s sims
__device__ float g_bsum_m[BB];         // per-batch sum of top-4 m sims

// 256-bit global load (non-coherent) / streaming store — sm_100+ PTX.
__device__ __forceinline__ void ldg_nc_v8(const float* p, float* v) {
    asm volatile("ld.global.nc.v8.f32 {%0,%1,%2,%3,%4,%5,%6,%7}, [%8];"
                 : "=f"(v[0]), "=f"(v[1]), "=f"(v[2]), "=f"(v[3]),
                   "=f"(v[4]), "=f"(v[5]), "=f"(v[6]), "=f"(v[7])
                 : "l"(p));
}
__device__ __forceinline__ void stg_cs_v8(float* p, const float* v) {
    asm volatile("st.global.cs.v8.f32 [%0], {%1,%2,%3,%4,%5,%6,%7,%8};"
                 :: "l"(p),
                    "f"(v[0]), "f"(v[1]), "f"(v[2]), "f"(v[3]),
                    "f"(v[4]), "f"(v[5]), "f"(v[6]), "f"(v[7])
                 : "memory");
}

// ---------------------------------------------------------------------------
// Kernel 1: fused per-batch mean (float4, 4 row-groups of 49) + L2-normalize
// + 40 similarity dots with on-the-fly key normalization + top-4 selection.
// Measured 29.8us. 256 blocks x 768 threads. __ldcs streaming reads of x.
// ---------------------------------------------------------------------------
__global__ void batch_sim_topk_kernel(const float4* __restrict__ x,
                                      const float4* __restrict__ skey,
                                      const float4* __restrict__ mkey) {
    int b = blockIdx.x;
    int t = threadIdx.x;   // 0..767
    int q = t / D4;        // row quarter 0..3 (49 rows each)
    int c4 = t % D4;       // float4 column 0..191

    __shared__ float4 sh4[768];     // partial sums (12 KB)
    __shared__ float4 sh_x4[D4];    // normalized mean (3 KB)
    __shared__ float  shw[8];
    __shared__ float  sh_sim[NKEYS];

    const float4* src = x + (size_t)b * (SEQ * D4) + (size_t)(q * 49) * D4 + c4;
    float4 acc = make_float4(0.f, 0.f, 0.f, 0.f);
    #pragma unroll 7
    for (int r = 0; r < 49; ++r) {
        float4 v = __ldcs(&src[(size_t)r * D4]);   // streaming (evict-first)
        acc.x += v.x; acc.y += v.y; acc.z += v.z; acc.w += v.w;
    }
    sh4[t] = acc;
    __syncthreads();

    float sq = 0.f;
    if (t < D4) {
        float4 a = sh4[t], b1 = sh4[t + D4], c = sh4[t + 2 * D4], d = sh4[t + 3 * D4];
        float4 m;
        m.x = (a.x + b1.x + c.x + d.x) * (1.0f / SEQ);
        m.y = (a.y + b1.y + c.y + d.y) * (1.0f / SEQ);
        m.z = (a.z + b1.z + c.z + d.z) * (1.0f / SEQ);
        m.w = (a.w + b1.w + c.w + d.w) * (1.0f / SEQ);
        sh_x4[t] = m;
        sq = m.x * m.x + m.y * m.y + m.z * m.z + m.w * m.w;
    }
    #pragma unroll
    for (int o = 16; o > 0; o >>= 1) sq += __shfl_down_sync(0xffffffffu, sq, o);
    if (t < D4 && (t & 31) == 0) shw[t >> 5] = sq;
    __syncthreads();
    if (t < 32) {
        float v = (t < 6) ? shw[t] : 0.f;
        #pragma unroll
        for (int o = 4; o > 0; o >>= 1) v += __shfl_down_sync(0xffffffffu, v, o);
        if (t == 0) shw[0] = v;
    }
    __syncthreads();
    float inv = rsqrtf(fmaxf(shw[0], 1e-12f));
    if (t < D4) {
        float4 m = sh_x4[t];
        m.x *= inv; m.y *= inv; m.z *= inv; m.w *= inv;
        sh_x4[t] = m;
    }
    __syncthreads();

    int warp = t >> 5, lane = t & 31;
    for (int p = warp; p < NKEYS; p += 24) {
        const float4* kp = (p < NPOOL) ? (skey + (size_t)p * D4)
                                       : (mkey + (size_t)(p - NPOOL) * D4);
        float dot = 0.f, kk = 0.f;
        #pragma unroll
        for (int i = lane; i < D4; i += 32) {
            float4 xv = sh_x4[i], kv = __ldg(&kp[i]);
            dot += xv.x * kv.x + xv.y * kv.y + xv.z * kv.z + xv.w * kv.w;
            kk  += kv.x * kv.x + kv.y * kv.y + kv.z * kv.z + kv.w * kv.w;
        }
        #pragma unroll
        for (int o = 16; o > 0; o >>= 1) {
            dot += __shfl_down_sync(0xffffffffu, dot, o);
            kk  += __shfl_down_sync(0xffffffffu, kk, o);
        }
        if (lane == 0) sh_sim[p] = dot * rsqrtf(fmaxf(kk, 1e-12f));
    }
    __syncthreads();

    // Top-4 (descending, first-index ties — strict > scan from j=0).
    if (t < 2) {
        const float* sims = sh_sim + t * NPOOL;
        int* idx = t ? g_midx : g_sidx;
        float v[NPOOL];
        #pragma unroll
        for (int j = 0; j < NPOOL; ++j) v[j] = sims[j];
        float sum = 0.f;
        #pragma unroll
        for (int k = 0; k < KK; ++k) {
            float best = -1e30f; int bi = 0;
            #pragma unroll
            for (int j = 0; j < NPOOL; ++j) if (v[j] > best) { best = v[j]; bi = j; }
            idx[b * KK + k] = bi;
            sum += best;
            v[bi] = -1e30f;
        }
        if (t) g_bsum_m[b] = sum; else g_bsum_s[b] = sum;
    }
}

// ---------------------------------------------------------------------------
// Kernel 2: fused gather — one launch, grid 12288 x 480 threads.
// 480 threads == BLK8: each thread owns exactly ONE v8-group per chunk, so
// all 4 loads (distinct register buffers) issue before any store -> MLP=4
// per thread, ~245KB in-flight reads per SM. No tail predicates.
// Block 0 (first 256 threads) folds in the scalar reduction.
// ---------------------------------------------------------------------------
__global__ void __launch_bounds__(480)
gather_kernel(const float* __restrict__ s_prompt,
              const float* __restrict__ m_prompt,
              float* __restrict__ out,
              float* __restrict__ out_scalars) {
    int g = blockIdx.x;               // 0..12287
    int which = g >= NGB;
    int lb = which ? g - NGB : g;
    int l = lb >> 8;                  // / 256
    int b = lb & 255;
    int t = threadIdx.x;              // 0..479

    if (g == 0) {
        __shared__ float shs[8], shm[8];
        float ssum = (t < BB) ? g_bsum_s[t] : 0.f;
        float msum = (t < BB) ? g_bsum_m[t] : 0.f;
        #pragma unroll
        for (int o = 16; o > 0; o >>= 1) {
            ssum += __shfl_down_sync(0xffffffffu, ssum, o);
            msum += __shfl_down_sync(0xffffffffu, msum, o);
        }
        if (t < BB && (t & 31) == 0) { shs[t >> 5] = ssum; shm[t >> 5] = msum; }
        __syncthreads();
        if (t == 0) {
            float sv = 0.f, mv = 0.f;
            #pragma unroll
            for (int w = 0; w < 8; ++w) { sv += shs[w]; mv += shm[w]; }
            out_scalars[0] = sv * (1.0f / BB);
            out_scalars[1] = mv * (1.0f / BB);
        }
    }

    const int* idx = which ? g_midx : g_sidx;
    const float* prompt = which ? m_prompt : s_prompt;
    const float* lbase = prompt + (size_t)l * NPOOL * BLK;

    int i0 = idx[b * KK + 0], i1 = idx[b * KK + 1],
        i2 = idx[b * KK + 2], i3 = idx[b * KK + 3];

    float* dst = out + (size_t)g * PER_LB + (size_t)t * 8;

    // 4 independent loads first (MLP=4), then 4 stores.
    float a[8], c[8], d[8], e[8];
    ldg_nc_v8(lbase + (size_t)i0 * BLK + (size_t)t * 8, a);
    ldg_nc_v8(lbase + (size_t)i1 * BLK + (size_t)t * 8, c);
    ldg_nc_v8(lbase + (size_t)i2 * BLK + (size_t)t * 8, d);
    ldg_nc_v8(lbase + (size_t)i3 * BLK + (size_t)t * 8, e);
    stg_cs_v8(dst,            a);
    stg_cs_v8(dst + BLK,      c);
    stg_cs_v8(dst + 2 * BLK,  d);
    stg_cs_v8(dst + 3 * BLK,  e);
}

// ---------------------------------------------------------------------------
extern "C" void kernel_launch(void* const* d_in, const int* in_sizes, int n_in,
                              void* d_out, int out_size) {
    const float* x_embed = (const float*)d_in[0];  // [256,196,768]
    const float* s_prompt = (const float*)d_in[1]; // [24,20,5,12,64]
    const float* m_prompt = (const float*)d_in[2]; // [24,20,5,12,64]
    const float* s_key = (const float*)d_in[3];    // [20,768]
    const float* m_key = (const float*)d_in[4];    // [20,768]
    float* out = (float*)d_out;

    const size_t S_ELEMS = (size_t)L2N * BB * PER_LB;  // 94,371,840
    float* out_scalars = out + 2 * S_ELEMS;

    batch_sim_topk_kernel<<<BB, 768>>>((const float4*)x_embed,
                                       (const float4*)s_key,
                                       (const float4*)m_key);
    gather_kernel<<<2 * NGB, 480>>>(s_prompt, m_prompt, out, out_scalars);
}